// round 2
// baseline (speedup 1.0000x reference)
#include <cuda_runtime.h>
#include <cuda_bf16.h>
#include <cooperative_groups.h>
#include <math.h>

namespace cg = cooperative_groups;

// Problem constants
#define PB   64
#define PT   2048
#define PH   256
#define PV   512
#define PVD  8
#define PD   128

// Scratch (static device arrays: allowed; runtime allocs are not)
__device__ float g_Xp[(size_t)PB * PT * PH];  // inputs @ W_ih.T + b  (B*T, H)
__device__ float g_H [(size_t)PB * PT * PH];  // hidden states       (B*T, H)

// ---------------------------------------------------------------------------
// GEMM (NT): C[m][n] = sum_k A[m][k] * B[n][k] + bias1[n] + bias2[n]
// A: MxK row-major, B: NxK row-major. Tiles 128x128x16, 256 thr, 8x8 micro.
// M % 128 == 0, N % 128 == 0, K % 16 == 0 (holds for our shapes).
// dstXp != 0 -> write to g_Xp (ignore C);  srcH != 0 -> read A from g_H.
// (Flags instead of symbol addresses: no runtime API calls during capture.)
// ---------------------------------------------------------------------------
__global__ __launch_bounds__(256) void gemm_nt(
    const float* __restrict__ A_in, const float* __restrict__ Bm,
    const float* __restrict__ bias1, const float* __restrict__ bias2,
    float* __restrict__ C_in, int M, int N, int K, int dstXp, int srcH)
{
    const float* A = srcH ? (const float*)g_H : A_in;
    float* C = dstXp ? (float*)g_Xp : C_in;

    __shared__ float As[16][132];
    __shared__ float Bs[16][132];

    const int tid = threadIdx.x;
    const int m0 = blockIdx.x * 128;
    const int n0 = blockIdx.y * 128;

    const int r = tid >> 2;         // 0..63
    const int c = (tid & 3) * 4;    // 0,4,8,12

    const float* Ap = A + (size_t)(m0 + r) * K + c;
    const float* Bp = Bm + (size_t)(n0 + r) * K + c;

    const int ty = tid >> 4;        // 0..15
    const int tx = tid & 15;        // 0..15

    float acc[8][8];
    #pragma unroll
    for (int i = 0; i < 8; i++)
        #pragma unroll
        for (int j = 0; j < 8; j++) acc[i][j] = 0.f;

    for (int k0 = 0; k0 < K; k0 += 16) {
        float4 a0 = *(const float4*)(Ap + k0);
        float4 a1 = *(const float4*)(Ap + k0 + (size_t)64 * K);
        float4 b0 = *(const float4*)(Bp + k0);
        float4 b1 = *(const float4*)(Bp + k0 + (size_t)64 * K);

        __syncthreads();  // previous tile fully consumed before overwrite
        As[c+0][r] = a0.x; As[c+1][r] = a0.y; As[c+2][r] = a0.z; As[c+3][r] = a0.w;
        As[c+0][r+64] = a1.x; As[c+1][r+64] = a1.y; As[c+2][r+64] = a1.z; As[c+3][r+64] = a1.w;
        Bs[c+0][r] = b0.x; Bs[c+1][r] = b0.y; Bs[c+2][r] = b0.z; Bs[c+3][r] = b0.w;
        Bs[c+0][r+64] = b1.x; Bs[c+1][r+64] = b1.y; Bs[c+2][r+64] = b1.z; Bs[c+3][r+64] = b1.w;
        __syncthreads();

        #pragma unroll
        for (int kk = 0; kk < 16; kk++) {
            float4 av0 = *(const float4*)&As[kk][ty * 8];
            float4 av1 = *(const float4*)&As[kk][ty * 8 + 4];
            float4 bv0 = *(const float4*)&Bs[kk][tx * 8];
            float4 bv1 = *(const float4*)&Bs[kk][tx * 8 + 4];
            float a_[8] = {av0.x, av0.y, av0.z, av0.w, av1.x, av1.y, av1.z, av1.w};
            float b_[8] = {bv0.x, bv0.y, bv0.z, bv0.w, bv1.x, bv1.y, bv1.z, bv1.w};
            #pragma unroll
            for (int i = 0; i < 8; i++)
                #pragma unroll
                for (int j = 0; j < 8; j++)
                    acc[i][j] = fmaf(a_[i], b_[j], acc[i][j]);
        }
    }

    const int nbase = n0 + tx * 8;
    float bs[8];
    #pragma unroll
    for (int j = 0; j < 8; j++) {
        float b = 0.f;
        if (bias1) b += bias1[nbase + j];
        if (bias2) b += bias2[nbase + j];
        bs[j] = b;
    }
    #pragma unroll
    for (int i = 0; i < 8; i++) {
        const int m = m0 + ty * 8 + i;
        float4 o0 = make_float4(acc[i][0]+bs[0], acc[i][1]+bs[1], acc[i][2]+bs[2], acc[i][3]+bs[3]);
        float4 o1 = make_float4(acc[i][4]+bs[4], acc[i][5]+bs[5], acc[i][6]+bs[6], acc[i][7]+bs[7]);
        *(float4*)&C[(size_t)m * N + nbase]     = o0;
        *(float4*)&C[(size_t)m * N + nbase + 4] = o1;
    }
}

// ---------------------------------------------------------------------------
// Sequential scan. 128 CTAs = 64 clusters of 2 (one cluster per batch).
// Each CTA owns 128 rows of W_hh in registers (64 fp32/thread) and computes
// half of hidden_new; halves exchanged via DSMEM + one cluster.sync per step.
// sh_h is double-buffered so a single cluster rendezvous per step is race-free:
// peer writes to buffer buf(t) occur only after the step-t rendezvous, my reads
// of buf(t) occur only before it.
// ---------------------------------------------------------------------------
__global__ void __cluster_dims__(2, 1, 1) __launch_bounds__(512, 1)
scan_kernel(const float* __restrict__ stack0, const float* __restrict__ hidden0,
            const float* __restrict__ W_hh, const float* __restrict__ W_sh,
            const float* __restrict__ W_a, const float* __restrict__ W_n,
            float* __restrict__ out)
{
    cg::cluster_group cluster = cg::this_cluster();

    __shared__ float sh_hbuf[2][PH];      // double-buffered full hidden
    __shared__ float sh_ht[PH];           // h_tilde
    __shared__ float sh_stack[2][PD * PVD];
    __shared__ float sh_Wsh[PH * PVD];    // W_sh row-major (k*8+d)
    __shared__ float sh_Wan[11 * PH];     // rows 0..2 = W_a, 3..10 = W_n
    __shared__ float sh_dots[11];
    __shared__ float sh_a[3];
    __shared__ float sh_n[PVD];

    const int tid   = threadIdx.x;
    const int batch = blockIdx.x >> 1;
    const int half  = blockIdx.x & 1;
    const int jl    = tid >> 2;           // 0..127: local output row
    const int q     = tid & 3;            // quarter of K dim
    const int jg    = half * 128 + jl;    // global hidden index owned

    // Register-resident W_hh slice: row jg, cols [q*64, q*64+64)
    float4 w4[16];
    {
        const float4* wrow = (const float4*)(W_hh + (size_t)jg * PH + q * 64);
        #pragma unroll
        for (int i = 0; i < 16; i++) w4[i] = wrow[i];
    }

    if (tid < PH) sh_hbuf[0][tid] = hidden0[batch * PH + tid];
    for (int e = tid; e < PD * PVD; e += 512) sh_stack[0][e] = stack0[batch * PD * PVD + e];
    for (int e = tid; e < PH * PVD; e += 512) sh_Wsh[e] = W_sh[e];
    for (int e = tid; e < 3 * PH;  e += 512) sh_Wan[e] = W_a[e];
    for (int e = tid; e < PVD * PH; e += 512) sh_Wan[3 * PH + e] = W_n[e];

    float* peer_hb = cluster.map_shared_rank(&sh_hbuf[0][0], half ^ 1);

    float xp = 0.f;
    if (q == 0) xp = g_Xp[((size_t)batch * PT) * PH + jg];  // t = 0 prefetch

    __syncthreads();
    cluster.sync();

    for (int t = 0; t < PT; t++) {
        const int buf  = t & 1;
        const int nbuf = buf ^ 1;

        // 1) h_tilde = h + stack_top @ W_sh.T
        if (tid < PH) {
            const float* wk = &sh_Wsh[tid * PVD];
            float s = sh_hbuf[buf][tid];
            #pragma unroll
            for (int d = 0; d < PVD; d++) s = fmaf(sh_stack[buf][d], wk[d], s);
            sh_ht[tid] = s;
        }
        __syncthreads();

        // 2) recurrent matvec: partial over 64 k-values, reduce across 4 lanes
        float acc = 0.f;
        const float4* hv4 = (const float4*)&sh_ht[q * 64];
        #pragma unroll
        for (int i = 0; i < 16; i++) {
            float4 h4 = hv4[i];
            acc = fmaf(h4.x, w4[i].x, acc);
            acc = fmaf(h4.y, w4[i].y, acc);
            acc = fmaf(h4.z, w4[i].z, acc);
            acc = fmaf(h4.w, w4[i].w, acc);
        }
        acc += __shfl_xor_sync(0xffffffffu, acc, 1);
        acc += __shfl_xor_sync(0xffffffffu, acc, 2);
        if (q == 0) {
            const float hn = tanhf(acc + xp);
            sh_hbuf[nbuf][jg] = hn;
            peer_hb[nbuf * PH + jg] = hn;
            if (t + 1 < PT)
                xp = g_Xp[((size_t)batch * PT + t + 1) * PH + jg];  // prefetch
        }
        cluster.sync();  // both halves of hidden_new visible everywhere

        // store hidden_new (own half) for the deferred y GEMM
        if (tid < 128)
            g_H[((size_t)batch * PT + t) * PH + half * 128 + tid] =
                sh_hbuf[nbuf][half * 128 + tid];

        // 3) a/n dot products: warp w computes row w of [W_a; W_n]
        {
            const int wid = tid >> 5, lane = tid & 31;
            if (wid < 11) {
                const float* wr = &sh_Wan[wid * PH];
                const float* hc = &sh_hbuf[nbuf][0];
                float p = 0.f;
                #pragma unroll
                for (int i = 0; i < 8; i++)
                    p = fmaf(hc[lane + 32 * i], wr[lane + 32 * i], p);
                #pragma unroll
                for (int o = 16; o > 0; o >>= 1)
                    p += __shfl_xor_sync(0xffffffffu, p, o);
                if (lane == 0) sh_dots[wid] = p;
            }
        }
        __syncthreads();

        // 4) softmax(a), sigmoid(n)
        if (tid == 0) {
            const float d0 = sh_dots[0], d1 = sh_dots[1], d2 = sh_dots[2];
            const float mx = fmaxf(d0, fmaxf(d1, d2));
            const float e0 = expf(d0 - mx), e1 = expf(d1 - mx), e2 = expf(d2 - mx);
            const float inv = 1.f / (e0 + e1 + e2);
            sh_a[0] = e0 * inv; sh_a[1] = e1 * inv; sh_a[2] = e2 * inv;
        } else if (tid >= 32 && tid < 32 + PVD) {
            sh_n[tid - 32] = 1.f / (1.f + expf(-sh_dots[3 + (tid - 32)]));
        }
        __syncthreads();

        // 5) stack blend: new = a0*push + a1*pop + a2*stay (replicated per CTA)
        {
            const float a0 = sh_a[0], a1 = sh_a[1], a2 = sh_a[2];
            #pragma unroll
            for (int rr = 0; rr < 2; rr++) {
                const int e = tid + rr * 512;
                const int p = e >> 3, d = e & 7;
                const float push = (p == 0)       ? sh_n[d]            : sh_stack[buf][e - 8];
                const float pop  = (p == PD - 1)  ? 0.f                : sh_stack[buf][e + 8];
                sh_stack[nbuf][e] = a0 * push + a1 * pop + a2 * sh_stack[buf][e];
            }
        }
        __syncthreads();
    }

    // Final state outputs. Parity: T even -> final stack/hidden in buffer 0.
    const size_t OUT_Y = (size_t)PB * PT * PV;
    if (half == 0) {
        for (int e = tid; e < PD * PVD; e += 512)
            out[OUT_Y + (size_t)batch * PD * PVD + e] = sh_stack[0][e];
    }
    if (tid < 128)
        out[OUT_Y + (size_t)PB * PD * PVD + (size_t)batch * PH + half * 128 + tid] =
            sh_hbuf[0][half * 128 + tid];
}

// ---------------------------------------------------------------------------
extern "C" void kernel_launch(void* const* d_in, const int* in_sizes, int n_in,
                              void* d_out, int out_size)
{
    const float* inputs  = (const float*)d_in[0];
    const float* stack0  = (const float*)d_in[1];
    const float* hidden0 = (const float*)d_in[2];
    const float* W_ih    = (const float*)d_in[3];
    const float* b_ih    = (const float*)d_in[4];
    const float* W_hh    = (const float*)d_in[5];
    const float* b_hh    = (const float*)d_in[6];
    const float* W_sh    = (const float*)d_in[7];
    const float* W_y     = (const float*)d_in[8];
    const float* W_a     = (const float*)d_in[9];
    const float* W_n     = (const float*)d_in[10];
    float* out = (float*)d_out;

    const int M = PB * PT;  // 131072

    // Phase 1: g_Xp = inputs @ W_ih.T + (b_ih + b_hh)
    gemm_nt<<<dim3(M / 128, PH / 128), 256>>>(inputs, W_ih, b_ih, b_hh,
                                              nullptr, M, PH, PV, /*dstXp=*/1, /*srcH=*/0);
    // Phase 2: sequential scan (stores hidden states to g_H, final stack/hidden)
    scan_kernel<<<2 * PB, 512>>>(stack0, hidden0, W_hh, W_sh, W_a, W_n, out);
    // Phase 3: outputs = g_H @ W_y.T
    gemm_nt<<<dim3(M / 128, PV / 128), 256>>>(nullptr, W_y, nullptr, nullptr,
                                              out, M, PV, PH, /*dstXp=*/0, /*srcH=*/1);
}

// round 4
// speedup vs baseline: 1.0367x; 1.0367x over previous
#include <cuda_runtime.h>
#include <cuda_bf16.h>
#include <math.h>
#include <stdint.h>

// Problem constants
#define PB   64
#define PT   2048
#define PH   256
#define PV   512
#define PVD  8
#define PD   128

// Scratch
__device__ float g_Xp[(size_t)PB * PT * PH];   // inputs @ W_ih.T + b
__device__ float g_H [(size_t)PB * PT * PH];   // hidden states
__device__ float g_Wfold[PH * PVD];            // W_hh @ W_sh  (256 x 8)

// ---- f32x2 packed-FMA helpers (sm_103a FFMA2) ------------------------------
#define FMA2(d,a,b,c) asm("fma.rn.f32x2 %0, %1, %2, %3;" : "=l"(d) : "l"(a), "l"(b), "l"(c))
#define ADD2(d,a,b)   asm("add.rn.f32x2 %0, %1, %2;"     : "=l"(d) : "l"(a), "l"(b))
#define PACK2(d,lo,hi) asm("mov.b64 %0, {%1, %2};" : "=l"(d) : "r"(__float_as_uint(lo)), "r"(__float_as_uint(hi)))
#define UNPACK2(lo,hi,s) do { unsigned _ulo, _uhi; \
    asm("mov.b64 {%0, %1}, %2;" : "=r"(_ulo), "=r"(_uhi) : "l"(s)); \
    lo = __uint_as_float(_ulo); hi = __uint_as_float(_uhi); } while (0)

__device__ __forceinline__ uint32_t s2u(const void* p) {
    uint32_t a;
    asm("{ .reg .u64 t; cvta.to.shared.u64 t, %1; cvt.u32.u64 %0, t; }" : "=r"(a) : "l"(p));
    return a;
}

// ---------------------------------------------------------------------------
// Wfold[j][d] = sum_k W_hh[j][k] * W_sh[k][d]   (256 x 8, tiny)
// ---------------------------------------------------------------------------
__global__ void fold_kernel(const float* __restrict__ W_hh,
                            const float* __restrict__ W_sh)
{
    int idx = blockIdx.x * blockDim.x + threadIdx.x;   // 0..2047
    if (idx >= PH * PVD) return;
    int j = idx >> 3, d = idx & 7;
    float s = 0.f;
    for (int k = 0; k < PH; k++)
        s = fmaf(W_hh[j * PH + k], W_sh[k * PVD + d], s);
    g_Wfold[idx] = s;
}

// ---------------------------------------------------------------------------
// GEMM (NT) with f32x2 packed FMAs: C[m][n] = sum_k A[m][k]*B[n][k] (+bias)
// Tiles 128x128x16, 256 thr, 8x8 micro (as 8x4 f32x2 pairs along n).
// ---------------------------------------------------------------------------
__global__ __launch_bounds__(256) void gemm_nt(
    const float* __restrict__ A_in, const float* __restrict__ Bm,
    const float* __restrict__ bias1, const float* __restrict__ bias2,
    float* __restrict__ C_in, int M, int N, int K, int dstXp, int srcH)
{
    const float* A = srcH ? (const float*)g_H : A_in;
    float* C = dstXp ? (float*)g_Xp : C_in;

    __shared__ float As[16][132];
    __shared__ float Bs[16][132];

    const int tid = threadIdx.x;
    const int m0 = blockIdx.x * 128;
    const int n0 = blockIdx.y * 128;

    const int r = tid >> 2;
    const int c = (tid & 3) * 4;

    const float* Ap = A + (size_t)(m0 + r) * K + c;
    const float* Bp = Bm + (size_t)(n0 + r) * K + c;

    const int ty = tid >> 4;
    const int tx = tid & 15;

    unsigned long long acc2[8][4];
    #pragma unroll
    for (int i = 0; i < 8; i++)
        #pragma unroll
        for (int j = 0; j < 4; j++) acc2[i][j] = 0ull;

    for (int k0 = 0; k0 < K; k0 += 16) {
        float4 a0 = *(const float4*)(Ap + k0);
        float4 a1 = *(const float4*)(Ap + k0 + (size_t)64 * K);
        float4 b0 = *(const float4*)(Bp + k0);
        float4 b1 = *(const float4*)(Bp + k0 + (size_t)64 * K);

        __syncthreads();
        As[c+0][r] = a0.x; As[c+1][r] = a0.y; As[c+2][r] = a0.z; As[c+3][r] = a0.w;
        As[c+0][r+64] = a1.x; As[c+1][r+64] = a1.y; As[c+2][r+64] = a1.z; As[c+3][r+64] = a1.w;
        Bs[c+0][r] = b0.x; Bs[c+1][r] = b0.y; Bs[c+2][r] = b0.z; Bs[c+3][r] = b0.w;
        Bs[c+0][r+64] = b1.x; Bs[c+1][r+64] = b1.y; Bs[c+2][r+64] = b1.z; Bs[c+3][r+64] = b1.w;
        __syncthreads();

        #pragma unroll
        for (int kk = 0; kk < 16; kk++) {
            float4 av0 = *(const float4*)&As[kk][ty * 8];
            float4 av1 = *(const float4*)&As[kk][ty * 8 + 4];
            float4 bv0 = *(const float4*)&Bs[kk][tx * 8];
            float4 bv1 = *(const float4*)&Bs[kk][tx * 8 + 4];
            unsigned long long bp0, bp1, bp2, bp3;
            PACK2(bp0, bv0.x, bv0.y); PACK2(bp1, bv0.z, bv0.w);
            PACK2(bp2, bv1.x, bv1.y); PACK2(bp3, bv1.z, bv1.w);
            float a_[8] = {av0.x, av0.y, av0.z, av0.w, av1.x, av1.y, av1.z, av1.w};
            #pragma unroll
            for (int i = 0; i < 8; i++) {
                unsigned long long ap;
                PACK2(ap, a_[i], a_[i]);
                FMA2(acc2[i][0], ap, bp0, acc2[i][0]);
                FMA2(acc2[i][1], ap, bp1, acc2[i][1]);
                FMA2(acc2[i][2], ap, bp2, acc2[i][2]);
                FMA2(acc2[i][3], ap, bp3, acc2[i][3]);
            }
        }
    }

    const int nbase = n0 + tx * 8;
    float bs[8];
    #pragma unroll
    for (int j = 0; j < 8; j++) {
        float b = 0.f;
        if (bias1) b += bias1[nbase + j];
        if (bias2) b += bias2[nbase + j];
        bs[j] = b;
    }
    #pragma unroll
    for (int i = 0; i < 8; i++) {
        const int m = m0 + ty * 8 + i;
        float a_[8];
        #pragma unroll
        for (int j4 = 0; j4 < 4; j4++)
            UNPACK2(a_[2*j4], a_[2*j4+1], acc2[i][j4]);
        float4 o0 = make_float4(a_[0]+bs[0], a_[1]+bs[1], a_[2]+bs[2], a_[3]+bs[3]);
        float4 o1 = make_float4(a_[4]+bs[4], a_[5]+bs[5], a_[6]+bs[6], a_[7]+bs[7]);
        *(float4*)&C[(size_t)m * N + nbase]     = o0;
        *(float4*)&C[(size_t)m * N + nbase + 4] = o1;
    }
}

// ---------------------------------------------------------------------------
// Sequential scan, 64 clusters of 2 CTAs (one cluster per batch), 512 thr/CTA.
// Per step: matvec (W_hh reg-resident, f32x2) + Wfold correction -> tanh ->
// DSMEM exchange via mbarrier release/acquire handshake -> dots -> softmax/
// sigmoid/new-top -> stack blend. 3 syncthreads + 1 handshake per step.
// ---------------------------------------------------------------------------
__global__ void __cluster_dims__(2, 1, 1) __launch_bounds__(512, 1)
scan_kernel(const float* __restrict__ stack0, const float* __restrict__ hidden0,
            const float* __restrict__ W_hh, const float* __restrict__ W_a,
            const float* __restrict__ W_n, float* __restrict__ out)
{
    __shared__ __align__(16) float sh_h[2][PH];       // double-buffered hidden
    __shared__ float sh_stack[2][PD * PVD];
    __shared__ float sh_top[2][PVD];                  // stack row 0 per phase
    __shared__ float sh_Wan[11 * PH];                 // rows 0-2 W_a, 3-10 W_n
    __shared__ float sh_dots[11];
    __shared__ float sh_a[4];
    __shared__ float sh_n[PVD];
    __shared__ __align__(8) unsigned long long sh_bar;

    const int tid   = threadIdx.x;
    const int batch = blockIdx.x >> 1;
    const int half  = blockIdx.x & 1;
    const int jl    = tid >> 2;           // 0..127 output row (local)
    const int q     = tid & 3;            // quarter of K
    const int jg    = half * 128 + jl;

    // Register-resident W_hh slice as 32 f32x2 pairs (64 floats)
    unsigned long long wp[32];
    {
        const unsigned long long* wrow =
            (const unsigned long long*)(W_hh + (size_t)jg * PH + q * 64);
        #pragma unroll
        for (int i = 0; i < 32; i++) wp[i] = wrow[i];
    }
    const float wf0 = g_Wfold[jg * PVD + 2 * q];
    const float wf1 = g_Wfold[jg * PVD + 2 * q + 1];

    if (tid < PH) sh_h[0][tid] = hidden0[batch * PH + tid];
    for (int e = tid; e < PD * PVD; e += 512) sh_stack[0][e] = stack0[batch * PD * PVD + e];
    if (tid < PVD) sh_top[0][tid] = stack0[batch * PD * PVD + tid];
    for (int e = tid; e < 3 * PH;   e += 512) sh_Wan[e] = W_a[e];
    for (int e = tid; e < PVD * PH; e += 512) sh_Wan[3 * PH + e] = W_n[e];

    const uint32_t h_u32   = s2u(&sh_h[0][0]);
    const uint32_t bar_u32 = s2u(&sh_bar);
    uint32_t peer_h, peer_bar;
    const uint32_t prank = (uint32_t)(half ^ 1);
    asm("mapa.shared::cluster.u32 %0, %1, %2;" : "=r"(peer_h)   : "r"(h_u32),   "r"(prank));
    asm("mapa.shared::cluster.u32 %0, %1, %2;" : "=r"(peer_bar) : "r"(bar_u32), "r"(prank));

    if (tid == 0)
        asm volatile("mbarrier.init.shared.b64 [%0], 1;" :: "r"(bar_u32) : "memory");

    float xp_cur = 0.f;
    if (q == 0) xp_cur = g_Xp[((size_t)batch * PT) * PH + jg];

    __syncthreads();
    asm volatile("barrier.cluster.arrive.aligned;" ::: "memory");
    asm volatile("barrier.cluster.wait.aligned;"   ::: "memory");

    for (int t = 0; t < PT; t++) {
        const int buf  = t & 1;
        const int nbuf = buf ^ 1;

        float xp_next = 0.f;
        if (q == 0 && t + 1 < PT)
            xp_next = g_Xp[((size_t)batch * PT + t + 1) * PH + jg];

        // ---- recurrent matvec: out_j = W_hh[j,:]*h + Wfold[j,:]*s_top -----
        unsigned long long a0 = 0ull, a1 = 0ull, a2 = 0ull, a3 = 0ull;
        const unsigned long long* hp = (const unsigned long long*)&sh_h[buf][q * 64];
        #pragma unroll
        for (int i = 0; i < 32; i += 4) {
            FMA2(a0, wp[i+0], hp[i+0], a0);
            FMA2(a1, wp[i+1], hp[i+1], a1);
            FMA2(a2, wp[i+2], hp[i+2], a2);
            FMA2(a3, wp[i+3], hp[i+3], a3);
        }
        ADD2(a0, a0, a1); ADD2(a2, a2, a3); ADD2(a0, a0, a2);
        float lo, hi; UNPACK2(lo, hi, a0);
        float acc = lo + hi;
        acc = fmaf(wf0, sh_top[buf][2 * q],     acc);
        acc = fmaf(wf1, sh_top[buf][2 * q + 1], acc);
        acc += __shfl_xor_sync(0xffffffffu, acc, 1);
        acc += __shfl_xor_sync(0xffffffffu, acc, 2);
        if (q == 0) {
            const float hn = tanhf(acc + xp_cur);
            sh_h[nbuf][jg] = hn;
            asm volatile("st.shared::cluster.f32 [%0], %1;"
                         :: "r"(peer_h + (uint32_t)((nbuf * PH + jg) * 4)), "f"(hn)
                         : "memory");
        }
        xp_cur = xp_next;
        __syncthreads();                       // sync #1: stores done locally

        if (tid == 0)
            asm volatile("mbarrier.arrive.release.cluster.shared::cluster.b64 _, [%0];"
                         :: "r"(peer_bar) : "memory");
        {   // wait for peer's half of h(t+1)
            const uint32_t par = (uint32_t)(t & 1);
            uint32_t done;
            do {
                asm volatile("{\n\t.reg .pred P;\n\t"
                    "mbarrier.try_wait.parity.acquire.cluster.shared::cta.b64 P, [%1], %2, 0x989680;\n\t"
                    "selp.b32 %0, 1, 0, P;\n\t}"
                    : "=r"(done) : "r"(bar_u32), "r"(par) : "memory");
            } while (!done);
        }

        // ---- dots (warps 0..10) + g_H store (warps 12..15) ---------------
        const int wid = tid >> 5, lane = tid & 31;
        if (wid < 11) {
            const float* wr = &sh_Wan[wid * PH];
            const float* hc = &sh_h[nbuf][0];
            float p = 0.f;
            #pragma unroll
            for (int i = 0; i < 8; i++)
                p = fmaf(hc[lane + 32 * i], wr[lane + 32 * i], p);
            #pragma unroll
            for (int o = 16; o > 0; o >>= 1)
                p += __shfl_xor_sync(0xffffffffu, p, o);
            if (lane == 0) sh_dots[wid] = p;
        } else if (wid >= 12) {
            const int i = tid - 384;           // 0..127, coalesced
            g_H[((size_t)batch * PT + t) * PH + half * 128 + i] =
                sh_h[nbuf][half * 128 + i];
        }
        __syncthreads();                       // sync #2: sh_dots ready

        // ---- softmax / sigmoid / new stack top (warp 0) ------------------
        if (wid == 0) {
            const float d0 = sh_dots[0], d1 = sh_dots[1], d2 = sh_dots[2];
            const float mx = fmaxf(d0, fmaxf(d1, d2));
            const float e0 = __expf(d0 - mx), e1 = __expf(d1 - mx), e2 = __expf(d2 - mx);
            const float inv = 1.f / (e0 + e1 + e2);
            const float A0 = e0 * inv, A1 = e1 * inv, A2 = e2 * inv;
            if (lane == 0) { sh_a[0] = A0; sh_a[1] = A1; sh_a[2] = A2; }
            if (lane < PVD) {
                const float nd = 1.f / (1.f + __expf(-sh_dots[3 + lane]));
                sh_n[lane] = nd;
                sh_top[nbuf][lane] = A0 * nd
                                   + A1 * sh_stack[buf][8 + lane]
                                   + A2 * sh_stack[buf][lane];
            }
        }
        __syncthreads();                       // sync #3: a, n, top ready

        // ---- full stack blend (off critical path of next matvec) ---------
        {
            const float A0 = sh_a[0], A1 = sh_a[1], A2 = sh_a[2];
            #pragma unroll
            for (int rr = 0; rr < 2; rr++) {
                const int e = tid + rr * 512;
                const int p = e >> 3, d = e & 7;
                const float push = (p == 0)      ? sh_n[d] : sh_stack[buf][e - 8];
                const float pop  = (p == PD - 1) ? 0.f     : sh_stack[buf][e + 8];
                sh_stack[nbuf][e] = A0 * push + A1 * pop + A2 * sh_stack[buf][e];
            }
        }
        // no sync: next matvec reads sh_h[nbuf] (handshaked) and sh_top[nbuf]
        // (written before sync #3); sh_stack consumers are 2+ syncs away.
    }

    __syncthreads();
    // Final states: T even -> stack/hidden live in index-0 buffers.
    const size_t OUT_Y = (size_t)PB * PT * PV;
    if (half == 0) {
        for (int e = tid; e < PD * PVD; e += 512)
            out[OUT_Y + (size_t)batch * PD * PVD + e] = sh_stack[0][e];
    }
    if (tid < 128)
        out[OUT_Y + (size_t)PB * PD * PVD + (size_t)batch * PH + half * 128 + tid] =
            sh_h[0][half * 128 + tid];

    asm volatile("barrier.cluster.arrive.aligned;" ::: "memory");
    asm volatile("barrier.cluster.wait.aligned;"   ::: "memory");
}

// ---------------------------------------------------------------------------
extern "C" void kernel_launch(void* const* d_in, const int* in_sizes, int n_in,
                              void* d_out, int out_size)
{
    const float* inputs  = (const float*)d_in[0];
    const float* stack0  = (const float*)d_in[1];
    const float* hidden0 = (const float*)d_in[2];
    const float* W_ih    = (const float*)d_in[3];
    const float* b_ih    = (const float*)d_in[4];
    const float* W_hh    = (const float*)d_in[5];
    const float* b_hh    = (const float*)d_in[6];
    const float* W_sh    = (const float*)d_in[7];
    const float* W_y     = (const float*)d_in[8];
    const float* W_a     = (const float*)d_in[9];
    const float* W_n     = (const float*)d_in[10];
    float* out = (float*)d_out;

    const int M = PB * PT;  // 131072

    // Wfold = W_hh @ W_sh (tiny)
    fold_kernel<<<8, 256>>>(W_hh, W_sh);
    // Phase 1: g_Xp = inputs @ W_ih.T + (b_ih + b_hh)
    gemm_nt<<<dim3(M / 128, PH / 128), 256>>>(inputs, W_ih, b_ih, b_hh,
                                              nullptr, M, PH, PV, 1, 0);
    // Phase 2: sequential scan
    scan_kernel<<<2 * PB, 512>>>(stack0, hidden0, W_hh, W_a, W_n, out);
    // Phase 3: outputs = g_H @ W_y.T
    gemm_nt<<<dim3(M / 128, PV / 128), 256>>>(nullptr, W_y, nullptr, nullptr,
                                              out, M, PV, PH, 0, 1);
}

// round 6
// speedup vs baseline: 1.7339x; 1.6724x over previous
#include <cuda_runtime.h>
#include <cuda_bf16.h>
#include <math.h>
#include <stdint.h>

// Problem constants
#define PB   64
#define PT   2048
#define PH   256
#define PV   512
#define PVD  8
#define PD   128

// Scratch
__device__ float g_Xp[(size_t)PB * PT * PH];   // inputs @ W_ih.T + b
__device__ float g_H [(size_t)PB * PT * PH];   // hidden states
__device__ float g_Wfold[PH * PVD];            // W_hh @ W_sh  (256 x 8)

// ---- f32x2 packed-FMA helpers (sm_103a FFMA2) ------------------------------
#define FMA2(d,a,b,c) asm("fma.rn.f32x2 %0, %1, %2, %3;" : "=l"(d) : "l"(a), "l"(b), "l"(c))
#define ADD2(d,a,b)   asm("add.rn.f32x2 %0, %1, %2;"     : "=l"(d) : "l"(a), "l"(b))
#define PACK2(d,lo,hi) asm("mov.b64 %0, {%1, %2};" : "=l"(d) : "r"(__float_as_uint(lo)), "r"(__float_as_uint(hi)))
#define UNPACK2(lo,hi,s) do { unsigned _ulo, _uhi; \
    asm("mov.b64 {%0, %1}, %2;" : "=r"(_ulo), "=r"(_uhi) : "l"(s)); \
    lo = __uint_as_float(_ulo); hi = __uint_as_float(_uhi); } while (0)

__device__ __forceinline__ uint32_t s2u(const void* p) {
    uint32_t a;
    asm("{ .reg .u64 t; cvta.to.shared.u64 t, %1; cvt.u32.u64 %0, t; }" : "=r"(a) : "l"(p));
    return a;
}

// ---------------------------------------------------------------------------
// Wfold[j][d] = sum_k W_hh[j][k] * W_sh[k][d]   (256 x 8, tiny)
// ---------------------------------------------------------------------------
__global__ void fold_kernel(const float* __restrict__ W_hh,
                            const float* __restrict__ W_sh)
{
    int idx = blockIdx.x * blockDim.x + threadIdx.x;
    if (idx >= PH * PVD) return;
    int j = idx >> 3, d = idx & 7;
    float s = 0.f;
    for (int k = 0; k < PH; k++)
        s = fmaf(W_hh[j * PH + k], W_sh[k * PVD + d], s);
    g_Wfold[idx] = s;
}

// ---------------------------------------------------------------------------
// GEMM (NT), f32x2 FMAs, conflict-free micro-tile:
// thread (ty,tx) owns rows {ty*4+i, 64+ty*4+i} and cols {tx*4+j, 64+tx*4+j}.
// B loads are consecutive float4s across lanes (2-phase, minimal); A loads
// broadcast; b-operands arrive pre-packed for fma.rn.f32x2.
// ---------------------------------------------------------------------------
__global__ __launch_bounds__(256) void gemm_nt(
    const float* __restrict__ A_in, const float* __restrict__ Bm,
    const float* __restrict__ bias1, const float* __restrict__ bias2,
    float* __restrict__ C_in, int M, int N, int K, int dstXp, int srcH)
{
    const float* A = srcH ? (const float*)g_H : A_in;
    float* C = dstXp ? (float*)g_Xp : C_in;

    __shared__ __align__(16) float As[16][132];
    __shared__ __align__(16) float Bs[16][132];

    const int tid = threadIdx.x;
    const int m0 = blockIdx.x * 128;
    const int n0 = blockIdx.y * 128;

    const int r = tid >> 2;
    const int c = (tid & 3) * 4;

    const float* Ap = A + (size_t)(m0 + r) * K + c;
    const float* Bp = Bm + (size_t)(n0 + r) * K + c;

    const int ty = tid >> 4;        // 0..15
    const int tx = tid & 15;        // 0..15

    unsigned long long acc2[8][4];  // [row 0..7][col-pair 0..3]
    #pragma unroll
    for (int i = 0; i < 8; i++)
        #pragma unroll
        for (int j = 0; j < 4; j++) acc2[i][j] = 0ull;

    for (int k0 = 0; k0 < K; k0 += 16) {
        float4 a0 = *(const float4*)(Ap + k0);
        float4 a1 = *(const float4*)(Ap + k0 + (size_t)64 * K);
        float4 b0 = *(const float4*)(Bp + k0);
        float4 b1 = *(const float4*)(Bp + k0 + (size_t)64 * K);

        __syncthreads();
        As[c+0][r] = a0.x; As[c+1][r] = a0.y; As[c+2][r] = a0.z; As[c+3][r] = a0.w;
        As[c+0][r+64] = a1.x; As[c+1][r+64] = a1.y; As[c+2][r+64] = a1.z; As[c+3][r+64] = a1.w;
        Bs[c+0][r] = b0.x; Bs[c+1][r] = b0.y; Bs[c+2][r] = b0.z; Bs[c+3][r] = b0.w;
        Bs[c+0][r+64] = b1.x; Bs[c+1][r+64] = b1.y; Bs[c+2][r+64] = b1.z; Bs[c+3][r+64] = b1.w;
        __syncthreads();

        #pragma unroll
        for (int kk = 0; kk < 16; kk++) {
            const float4* Arow = (const float4*)&As[kk][0];
            float4 av0 = Arow[ty];          // rows ty*4..+3
            float4 av1 = Arow[16 + ty];     // rows 64+ty*4..+3
            const ulonglong2* Brow = (const ulonglong2*)&Bs[kk][0];
            ulonglong2 bp01 = Brow[tx];     // cols tx*4..+3 (2 packed pairs)
            ulonglong2 bp23 = Brow[16 + tx];// cols 64+tx*4..+3
            float a_[8] = {av0.x, av0.y, av0.z, av0.w, av1.x, av1.y, av1.z, av1.w};
            #pragma unroll
            for (int i = 0; i < 8; i++) {
                unsigned long long ap;
                PACK2(ap, a_[i], a_[i]);
                FMA2(acc2[i][0], ap, bp01.x, acc2[i][0]);
                FMA2(acc2[i][1], ap, bp01.y, acc2[i][1]);
                FMA2(acc2[i][2], ap, bp23.x, acc2[i][2]);
                FMA2(acc2[i][3], ap, bp23.y, acc2[i][3]);
            }
        }
    }

    const int nb0 = n0 + tx * 4;
    const int nb1 = n0 + 64 + tx * 4;
    float bs0[4], bs1[4];
    #pragma unroll
    for (int j = 0; j < 4; j++) {
        float b0v = 0.f, b1v = 0.f;
        if (bias1) { b0v += bias1[nb0 + j]; b1v += bias1[nb1 + j]; }
        if (bias2) { b0v += bias2[nb0 + j]; b1v += bias2[nb1 + j]; }
        bs0[j] = b0v; bs1[j] = b1v;
    }
    #pragma unroll
    for (int i = 0; i < 8; i++) {
        const int m = m0 + (i < 4 ? ty * 4 + i : 64 + ty * 4 + (i - 4));
        float v[8];
        #pragma unroll
        for (int j4 = 0; j4 < 4; j4++) UNPACK2(v[2*j4], v[2*j4+1], acc2[i][j4]);
        float4 o0 = make_float4(v[0]+bs0[0], v[1]+bs0[1], v[2]+bs0[2], v[3]+bs0[3]);
        float4 o1 = make_float4(v[4]+bs1[0], v[5]+bs1[1], v[6]+bs1[2], v[7]+bs1[3]);
        *(float4*)&C[(size_t)m * N + nb0] = o0;
        *(float4*)&C[(size_t)m * N + nb1] = o1;
    }
}

// ---------------------------------------------------------------------------
// Sequential scan, 64 clusters of 2 CTAs, 512 thr/CTA.
// h is stored in a PADDED per-quarter layout: slice q (k in [64q,64q+64)) at
// float offset q*68 -> slices start on banks {0,4,8,12}: LDS.128 matvec loads
// are conflict-free (1 wavefront/instr instead of 4).
// ---------------------------------------------------------------------------
#define HPAD 68
#define HBUF (4 * HPAD)   // 272 floats per h buffer
__device__ __forceinline__ int hpad_idx(int k) { return (k >> 6) * HPAD + (k & 63); }

__global__ void __cluster_dims__(2, 1, 1) __launch_bounds__(512, 1)
scan_kernel(const float* __restrict__ stack0, const float* __restrict__ hidden0,
            const float* __restrict__ W_hh, const float* __restrict__ W_a,
            const float* __restrict__ W_n, float* __restrict__ out)
{
    __shared__ __align__(16) float sh_h[2][HBUF];     // double-buffered, padded
    __shared__ float sh_stack[2][PD * PVD];
    __shared__ float sh_top[2][PVD];
    __shared__ float sh_Wan[11 * PH];
    __shared__ float sh_dots[11];
    __shared__ float sh_a[4];
    __shared__ float sh_n[PVD];
    __shared__ __align__(8) unsigned long long sh_bar;

    const int tid   = threadIdx.x;
    const int batch = blockIdx.x >> 1;
    const int half  = blockIdx.x & 1;
    const int jl    = tid >> 2;           // 0..127 output row (local)
    const int q     = tid & 3;            // quarter of K
    const int jg    = half * 128 + jl;
    const int jgp   = hpad_idx(jg);       // padded position of own row

    // Register-resident W_hh slice as 32 f32x2 pairs (64 floats)
    unsigned long long wp[32];
    {
        const unsigned long long* wrow =
            (const unsigned long long*)(W_hh + (size_t)jg * PH + q * 64);
        #pragma unroll
        for (int i = 0; i < 32; i++) wp[i] = wrow[i];
    }
    const float wf0 = g_Wfold[jg * PVD + 2 * q];
    const float wf1 = g_Wfold[jg * PVD + 2 * q + 1];

    if (tid < PH) sh_h[0][hpad_idx(tid)] = hidden0[batch * PH + tid];
    for (int e = tid; e < PD * PVD; e += 512) sh_stack[0][e] = stack0[batch * PD * PVD + e];
    if (tid < PVD) sh_top[0][tid] = stack0[batch * PD * PVD + tid];
    for (int e = tid; e < 3 * PH;   e += 512) sh_Wan[e] = W_a[e];
    for (int e = tid; e < PVD * PH; e += 512) sh_Wan[3 * PH + e] = W_n[e];

    const uint32_t h_u32   = s2u(&sh_h[0][0]);
    const uint32_t bar_u32 = s2u(&sh_bar);
    uint32_t peer_h, peer_bar;
    const uint32_t prank = (uint32_t)(half ^ 1);
    asm("mapa.shared::cluster.u32 %0, %1, %2;" : "=r"(peer_h)   : "r"(h_u32),   "r"(prank));
    asm("mapa.shared::cluster.u32 %0, %1, %2;" : "=r"(peer_bar) : "r"(bar_u32), "r"(prank));

    if (tid == 0)
        asm volatile("mbarrier.init.shared.b64 [%0], 1;" :: "r"(bar_u32) : "memory");

    float xp_cur = 0.f;
    if (q == 0) xp_cur = g_Xp[((size_t)batch * PT) * PH + jg];

    __syncthreads();
    asm volatile("barrier.cluster.arrive.aligned;" ::: "memory");
    asm volatile("barrier.cluster.wait.aligned;"   ::: "memory");

    for (int t = 0; t < PT; t++) {
        const int buf  = t & 1;
        const int nbuf = buf ^ 1;

        float xp_next = 0.f;
        if (q == 0 && t + 1 < PT)
            xp_next = g_Xp[((size_t)batch * PT + t + 1) * PH + jg];

        // ---- matvec: out_j = W_hh[j,:]*h + Wfold[j,:]*s_top (conflict-free)
        unsigned long long a0 = 0ull, a1 = 0ull, a2 = 0ull, a3 = 0ull;
        const ulonglong2* hv = (const ulonglong2*)&sh_h[buf][q * HPAD];
        #pragma unroll
        for (int i = 0; i < 16; i += 2) {
            ulonglong2 h0 = hv[i], h1 = hv[i + 1];
            FMA2(a0, wp[2*i+0], h0.x, a0);
            FMA2(a1, wp[2*i+1], h0.y, a1);
            FMA2(a2, wp[2*i+2], h1.x, a2);
            FMA2(a3, wp[2*i+3], h1.y, a3);
        }
        ADD2(a0, a0, a1); ADD2(a2, a2, a3); ADD2(a0, a0, a2);
        float lo, hi; UNPACK2(lo, hi, a0);
        float acc = lo + hi;
        acc = fmaf(wf0, sh_top[buf][2 * q],     acc);
        acc = fmaf(wf1, sh_top[buf][2 * q + 1], acc);
        acc += __shfl_xor_sync(0xffffffffu, acc, 1);
        acc += __shfl_xor_sync(0xffffffffu, acc, 2);
        if (q == 0) {
            const float hn = tanhf(acc + xp_cur);
            sh_h[nbuf][jgp] = hn;
            asm volatile("st.shared::cluster.f32 [%0], %1;"
                         :: "r"(peer_h + (uint32_t)((nbuf * HBUF + jgp) * 4)), "f"(hn)
                         : "memory");
        }
        xp_cur = xp_next;
        __syncthreads();                       // sync #1: local stores done

        if (tid == 0)
            asm volatile("mbarrier.arrive.release.cluster.shared::cluster.b64 _, [%0];"
                         :: "r"(peer_bar) : "memory");
        {   // wait for peer's half of h(t+1)
            const uint32_t par = (uint32_t)(t & 1);
            uint32_t done;
            do {
                asm volatile("{\n\t.reg .pred P;\n\t"
                    "mbarrier.try_wait.parity.acquire.cluster.shared::cta.b64 P, [%1], %2, 0x989680;\n\t"
                    "selp.b32 %0, 1, 0, P;\n\t}"
                    : "=r"(done) : "r"(bar_u32), "r"(par) : "memory");
            } while (!done);
        }

        // ---- dots (warps 0..10) + g_H store (warps 12..15) ---------------
        const int wid = tid >> 5, lane = tid & 31;
        if (wid < 11) {
            const float* wr = &sh_Wan[wid * PH];
            float p = 0.f;
            #pragma unroll
            for (int i = 0; i < 8; i++)
                p = fmaf(sh_h[nbuf][(i >> 1) * HPAD + (i & 1) * 32 + lane],
                         wr[lane + 32 * i], p);
            #pragma unroll
            for (int o = 16; o > 0; o >>= 1)
                p += __shfl_xor_sync(0xffffffffu, p, o);
            if (lane == 0) sh_dots[wid] = p;
        } else if (wid >= 12) {
            const int i = tid - 384;           // 0..127, coalesced in gmem
            g_H[((size_t)batch * PT + t) * PH + half * 128 + i] =
                sh_h[nbuf][(half * 2 + (i >> 6)) * HPAD + (i & 63)];
        }
        __syncthreads();                       // sync #2: sh_dots ready

        // ---- softmax / sigmoid / new stack top (warp 0) ------------------
        if (wid == 0) {
            const float d0 = sh_dots[0], d1 = sh_dots[1], d2 = sh_dots[2];
            const float mx = fmaxf(d0, fmaxf(d1, d2));
            const float e0 = __expf(d0 - mx), e1 = __expf(d1 - mx), e2 = __expf(d2 - mx);
            const float inv = 1.f / (e0 + e1 + e2);
            const float A0 = e0 * inv, A1 = e1 * inv, A2 = e2 * inv;
            if (lane == 0) { sh_a[0] = A0; sh_a[1] = A1; sh_a[2] = A2; }
            if (lane < PVD) {
                const float nd = 1.f / (1.f + __expf(-sh_dots[3 + lane]));
                sh_n[lane] = nd;
                sh_top[nbuf][lane] = A0 * nd
                                   + A1 * sh_stack[buf][8 + lane]
                                   + A2 * sh_stack[buf][lane];
            }
        }
        __syncthreads();                       // sync #3: a, n, top ready

        // ---- full stack blend (off next matvec's critical path) ----------
        {
            const float A0 = sh_a[0], A1 = sh_a[1], A2 = sh_a[2];
            #pragma unroll
            for (int rr = 0; rr < 2; rr++) {
                const int e = tid + rr * 512;
                const int p = e >> 3, d = e & 7;
                const float push = (p == 0)      ? sh_n[d] : sh_stack[buf][e - 8];
                const float pop  = (p == PD - 1) ? 0.f     : sh_stack[buf][e + 8];
                sh_stack[nbuf][e] = A0 * push + A1 * pop + A2 * sh_stack[buf][e];
            }
        }
        // no sync needed: next matvec reads sh_h[nbuf] (handshaked) and
        // sh_top[nbuf] (written before sync #3); blend consumers 2+ syncs away.
    }

    __syncthreads();
    const size_t OUT_Y = (size_t)PB * PT * PV;
    if (half == 0) {
        for (int e = tid; e < PD * PVD; e += 512)
            out[OUT_Y + (size_t)batch * PD * PVD + e] = sh_stack[0][e];
    }
    if (tid < 128) {
        const int row = half * 128 + tid;
        out[OUT_Y + (size_t)PB * PD * PVD + (size_t)batch * PH + row] =
            sh_h[0][hpad_idx(row)];
    }

    asm volatile("barrier.cluster.arrive.aligned;" ::: "memory");
    asm volatile("barrier.cluster.wait.aligned;"   ::: "memory");
}

// ---------------------------------------------------------------------------
extern "C" void kernel_launch(void* const* d_in, const int* in_sizes, int n_in,
                              void* d_out, int out_size)
{
    const float* inputs  = (const float*)d_in[0];
    const float* stack0  = (const float*)d_in[1];
    const float* hidden0 = (const float*)d_in[2];
    const float* W_ih    = (const float*)d_in[3];
    const float* b_ih    = (const float*)d_in[4];
    const float* W_hh    = (const float*)d_in[5];
    const float* b_hh    = (const float*)d_in[6];
    const float* W_sh    = (const float*)d_in[7];
    const float* W_y     = (const float*)d_in[8];
    const float* W_a     = (const float*)d_in[9];
    const float* W_n     = (const float*)d_in[10];
    float* out = (float*)d_out;

    const int M = PB * PT;  // 131072

    fold_kernel<<<8, 256>>>(W_hh, W_sh);
    gemm_nt<<<dim3(M / 128, PH / 128), 256>>>(inputs, W_ih, b_ih, b_hh,
                                              nullptr, M, PH, PV, 1, 0);
    scan_kernel<<<2 * PB, 512>>>(stack0, hidden0, W_hh, W_a, W_n, out);
    gemm_nt<<<dim3(M / 128, PV / 128), 256>>>(nullptr, W_y, nullptr, nullptr,
                                              out, M, PV, PH, 0, 1);
}

// round 7
// speedup vs baseline: 1.8715x; 1.0794x over previous
#include <cuda_runtime.h>
#include <cuda_bf16.h>
#include <math.h>
#include <stdint.h>

// Problem constants
#define PB   64
#define PT   2048
#define PH   256
#define PV   512
#define PVD  8
#define PD   128

// Scratch
__device__ float g_Xp[(size_t)PB * PT * PH];   // inputs @ W_ih.T + b
__device__ float g_H [(size_t)PB * PT * PH];   // hidden states
__device__ float g_Wfold[PH * PVD];            // W_hh @ W_sh  (256 x 8)

// ---- f32x2 packed-FMA helpers (sm_103a FFMA2) ------------------------------
#define FMA2(d,a,b,c) asm("fma.rn.f32x2 %0, %1, %2, %3;" : "=l"(d) : "l"(a), "l"(b), "l"(c))
#define ADD2(d,a,b)   asm("add.rn.f32x2 %0, %1, %2;"     : "=l"(d) : "l"(a), "l"(b))
#define PACK2(d,lo,hi) asm("mov.b64 %0, {%1, %2};" : "=l"(d) : "r"(__float_as_uint(lo)), "r"(__float_as_uint(hi)))
#define UNPACK2(lo,hi,s) do { unsigned _ulo, _uhi; \
    asm("mov.b64 {%0, %1}, %2;" : "=r"(_ulo), "=r"(_uhi) : "l"(s)); \
    lo = __uint_as_float(_ulo); hi = __uint_as_float(_uhi); } while (0)

__device__ __forceinline__ uint32_t s2u(const void* p) {
    uint32_t a;
    asm("{ .reg .u64 t; cvta.to.shared.u64 t, %1; cvt.u32.u64 %0, t; }" : "=r"(a) : "l"(p));
    return a;
}

// fast tanh: MUFU-based, abs err ~1e-7, clamped to avoid inf/inf
__device__ __forceinline__ float fast_tanh(float x) {
    const float xc = fminf(fmaxf(x, -10.f), 10.f);
    const float e = __expf(2.f * xc);
    return __fdividef(e - 1.f, e + 1.f);
}

// ---------------------------------------------------------------------------
// Wfold[j][d] = sum_k W_hh[j][k] * W_sh[k][d]
// ---------------------------------------------------------------------------
__global__ void fold_kernel(const float* __restrict__ W_hh,
                            const float* __restrict__ W_sh)
{
    int idx = blockIdx.x * blockDim.x + threadIdx.x;
    if (idx >= PH * PVD) return;
    int j = idx >> 3, d = idx & 7;
    float s = 0.f;
    for (int k = 0; k < PH; k++)
        s = fmaf(W_hh[j * PH + k], W_sh[k * PVD + d], s);
    g_Wfold[idx] = s;
}

// ---------------------------------------------------------------------------
// GEMM (NT), f32x2 FMAs, conflict-free micro-tile, 2 CTAs/SM.
// ---------------------------------------------------------------------------
__global__ __launch_bounds__(256, 2) void gemm_nt(
    const float* __restrict__ A_in, const float* __restrict__ Bm,
    const float* __restrict__ bias1, const float* __restrict__ bias2,
    float* __restrict__ C_in, int M, int N, int K, int dstXp, int srcH)
{
    const float* A = srcH ? (const float*)g_H : A_in;
    float* C = dstXp ? (float*)g_Xp : C_in;

    __shared__ __align__(16) float As[16][132];
    __shared__ __align__(16) float Bs[16][132];

    const int tid = threadIdx.x;
    const int m0 = blockIdx.x * 128;
    const int n0 = blockIdx.y * 128;

    const int r = tid >> 2;
    const int c = (tid & 3) * 4;

    const float* Ap = A + (size_t)(m0 + r) * K + c;
    const float* Bp = Bm + (size_t)(n0 + r) * K + c;

    const int ty = tid >> 4;
    const int tx = tid & 15;

    unsigned long long acc2[8][4];
    #pragma unroll
    for (int i = 0; i < 8; i++)
        #pragma unroll
        for (int j = 0; j < 4; j++) acc2[i][j] = 0ull;

    for (int k0 = 0; k0 < K; k0 += 16) {
        float4 a0 = *(const float4*)(Ap + k0);
        float4 a1 = *(const float4*)(Ap + k0 + (size_t)64 * K);
        float4 b0 = *(const float4*)(Bp + k0);
        float4 b1 = *(const float4*)(Bp + k0 + (size_t)64 * K);

        __syncthreads();
        As[c+0][r] = a0.x; As[c+1][r] = a0.y; As[c+2][r] = a0.z; As[c+3][r] = a0.w;
        As[c+0][r+64] = a1.x; As[c+1][r+64] = a1.y; As[c+2][r+64] = a1.z; As[c+3][r+64] = a1.w;
        Bs[c+0][r] = b0.x; Bs[c+1][r] = b0.y; Bs[c+2][r] = b0.z; Bs[c+3][r] = b0.w;
        Bs[c+0][r+64] = b1.x; Bs[c+1][r+64] = b1.y; Bs[c+2][r+64] = b1.z; Bs[c+3][r+64] = b1.w;
        __syncthreads();

        #pragma unroll
        for (int kk = 0; kk < 16; kk++) {
            const float4* Arow = (const float4*)&As[kk][0];
            float4 av0 = Arow[ty];
            float4 av1 = Arow[16 + ty];
            const ulonglong2* Brow = (const ulonglong2*)&Bs[kk][0];
            ulonglong2 bp01 = Brow[tx];
            ulonglong2 bp23 = Brow[16 + tx];
            float a_[8] = {av0.x, av0.y, av0.z, av0.w, av1.x, av1.y, av1.z, av1.w};
            #pragma unroll
            for (int i = 0; i < 8; i++) {
                unsigned long long ap;
                PACK2(ap, a_[i], a_[i]);
                FMA2(acc2[i][0], ap, bp01.x, acc2[i][0]);
                FMA2(acc2[i][1], ap, bp01.y, acc2[i][1]);
                FMA2(acc2[i][2], ap, bp23.x, acc2[i][2]);
                FMA2(acc2[i][3], ap, bp23.y, acc2[i][3]);
            }
        }
    }

    const int nb0 = n0 + tx * 4;
    const int nb1 = n0 + 64 + tx * 4;
    float bs0[4], bs1[4];
    #pragma unroll
    for (int j = 0; j < 4; j++) {
        float b0v = 0.f, b1v = 0.f;
        if (bias1) { b0v += bias1[nb0 + j]; b1v += bias1[nb1 + j]; }
        if (bias2) { b0v += bias2[nb0 + j]; b1v += bias2[nb1 + j]; }
        bs0[j] = b0v; bs1[j] = b1v;
    }
    #pragma unroll
    for (int i = 0; i < 8; i++) {
        const int m = m0 + (i < 4 ? ty * 4 + i : 64 + ty * 4 + (i - 4));
        float v[8];
        #pragma unroll
        for (int j4 = 0; j4 < 4; j4++) UNPACK2(v[2*j4], v[2*j4+1], acc2[i][j4]);
        float4 o0 = make_float4(v[0]+bs0[0], v[1]+bs0[1], v[2]+bs0[2], v[3]+bs0[3]);
        float4 o1 = make_float4(v[4]+bs1[0], v[5]+bs1[1], v[6]+bs1[2], v[7]+bs1[3]);
        *(float4*)&C[(size_t)m * N + nb0] = o0;
        *(float4*)&C[(size_t)m * N + nb1] = o1;
    }
}

// ---------------------------------------------------------------------------
// Sequential scan — fused phase structure. Per iteration t (reads h_t):
//  A: all threads: W_hh·h_t partials from registers
//  B: warps 0-10: [W_a;W_n]·h_t dots (smem weights) + reduce; warps 12-15: g_H
//  C: sync  D: warp0: softmax/sigmoid -> a,n,top_t (t=0: identity blend)
//  E: sync  F: all: acc += Wfold·top_t, lane-reduce, tanh, store+DSMEM send
//  G: sync  H: arrive(peer)  I: stack blend (overlaps peer latency)  J: wait
// Race safety: all reads of h-buffer buf(t) precede H(t); the peer can only
// overwrite buf(t) (= its nbuf(t+1)) after receiving that arrive.
// ---------------------------------------------------------------------------
#define HPAD 68
#define HBUF (4 * HPAD)
__device__ __forceinline__ int hpad_idx(int k) { return (k >> 6) * HPAD + (k & 63); }

__global__ void __cluster_dims__(2, 1, 1) __launch_bounds__(512, 1)
scan_kernel(const float* __restrict__ stack0, const float* __restrict__ hidden0,
            const float* __restrict__ W_hh, const float* __restrict__ W_a,
            const float* __restrict__ W_n, float* __restrict__ out)
{
    __shared__ __align__(16) float sh_h[2][HBUF];
    __shared__ float sh_stack[2][PD * PVD];
    __shared__ float sh_Wan[11 * PH];
    __shared__ float sh_dots[11];
    __shared__ float sh_a[4];
    __shared__ float sh_n[PVD];
    __shared__ float sh_top[PVD];
    __shared__ __align__(8) unsigned long long sh_bar;

    const int tid   = threadIdx.x;
    const int batch = blockIdx.x >> 1;
    const int half  = blockIdx.x & 1;
    const int jl    = tid >> 2;
    const int q     = tid & 3;
    const int jg    = half * 128 + jl;
    const int jgp   = hpad_idx(jg);
    const int wid   = tid >> 5, lane = tid & 31;

    unsigned long long wp[32];
    {
        const unsigned long long* wrow =
            (const unsigned long long*)(W_hh + (size_t)jg * PH + q * 64);
        #pragma unroll
        for (int i = 0; i < 32; i++) wp[i] = wrow[i];
    }
    const float wf0 = g_Wfold[jg * PVD + 2 * q];
    const float wf1 = g_Wfold[jg * PVD + 2 * q + 1];

    if (tid < PH) sh_h[0][hpad_idx(tid)] = hidden0[batch * PH + tid];
    for (int e = tid; e < PD * PVD; e += 512) sh_stack[0][e] = stack0[batch * PD * PVD + e];
    for (int e = tid; e < 3 * PH;   e += 512) sh_Wan[e] = W_a[e];
    for (int e = tid; e < PVD * PH; e += 512) sh_Wan[3 * PH + e] = W_n[e];

    const uint32_t h_u32   = s2u(&sh_h[0][0]);
    const uint32_t bar_u32 = s2u(&sh_bar);
    uint32_t peer_h, peer_bar;
    const uint32_t prank = (uint32_t)(half ^ 1);
    asm("mapa.shared::cluster.u32 %0, %1, %2;" : "=r"(peer_h)   : "r"(h_u32),   "r"(prank));
    asm("mapa.shared::cluster.u32 %0, %1, %2;" : "=r"(peer_bar) : "r"(bar_u32), "r"(prank));

    if (tid == 0)
        asm volatile("mbarrier.init.shared.b64 [%0], 1;" :: "r"(bar_u32) : "memory");

    float xp_cur = 0.f;
    if (q == 0) xp_cur = g_Xp[((size_t)batch * PT) * PH + jg];

    __syncthreads();
    asm volatile("barrier.cluster.arrive.aligned;" ::: "memory");
    asm volatile("barrier.cluster.wait.aligned;"   ::: "memory");

    for (int t = 0; t < PT; t++) {
        const int buf  = t & 1;
        const int nbuf = buf ^ 1;

        float xp_next = 0.f;
        if (q == 0 && t + 1 < PT)
            xp_next = g_Xp[((size_t)batch * PT + t + 1) * PH + jg];

        // ---- A: main matvec partials (registers) --------------------------
        unsigned long long a0 = 0ull, a1 = 0ull, a2 = 0ull, a3 = 0ull;
        const ulonglong2* hv = (const ulonglong2*)&sh_h[buf][q * HPAD];
        #pragma unroll
        for (int i = 0; i < 16; i += 2) {
            ulonglong2 h0 = hv[i], h1 = hv[i + 1];
            FMA2(a0, wp[2*i+0], h0.x, a0);
            FMA2(a1, wp[2*i+1], h0.y, a1);
            FMA2(a2, wp[2*i+2], h1.x, a2);
            FMA2(a3, wp[2*i+3], h1.y, a3);
        }
        ADD2(a0, a0, a1); ADD2(a2, a2, a3); ADD2(a0, a0, a2);
        float lo, hi; UNPACK2(lo, hi, a0);
        float acc = lo + hi;

        // ---- B: gate dots on the SAME h (warps 0-10); g_H (warps 12-15) --
        if (wid < 11) {
            const float* wr = &sh_Wan[wid * PH];
            float p = 0.f;
            #pragma unroll
            for (int i = 0; i < 8; i++)
                p = fmaf(sh_h[buf][(i >> 1) * HPAD + (i & 1) * 32 + lane],
                         wr[lane + 32 * i], p);
            #pragma unroll
            for (int o = 16; o > 0; o >>= 1)
                p += __shfl_xor_sync(0xffffffffu, p, o);
            if (lane == 0) sh_dots[wid] = p;
        } else if (wid >= 12 && t > 0) {
            const int i = tid - 384;
            g_H[((size_t)batch * PT + t - 1) * PH + half * 128 + i] =
                sh_h[buf][(half * 2 + (i >> 6)) * HPAD + (i & 63)];
        }
        __syncthreads();                       // C

        // ---- D: softmax / sigmoid / top_t (warp 0) ------------------------
        if (wid == 0) {
            float A0, A1, A2;
            if (t == 0) { A0 = 0.f; A1 = 0.f; A2 = 1.f; }
            else {
                const float d0 = sh_dots[0], d1 = sh_dots[1], d2 = sh_dots[2];
                const float mx = fmaxf(d0, fmaxf(d1, d2));
                const float e0 = __expf(d0 - mx), e1 = __expf(d1 - mx), e2 = __expf(d2 - mx);
                const float inv = __fdividef(1.f, e0 + e1 + e2);
                A0 = e0 * inv; A1 = e1 * inv; A2 = e2 * inv;
            }
            if (lane == 0) { sh_a[0] = A0; sh_a[1] = A1; sh_a[2] = A2; }
            if (lane < PVD) {
                const float nd = (t == 0) ? 0.f
                               : __fdividef(1.f, 1.f + __expf(-sh_dots[3 + lane]));
                sh_n[lane] = nd;
                sh_top[lane] = A0 * nd
                             + A1 * sh_stack[buf][8 + lane]
                             + A2 * sh_stack[buf][lane];
            }
        }
        __syncthreads();                       // E

        // ---- F: Wfold tail + reduce + tanh + exchange ---------------------
        acc = fmaf(wf0, sh_top[2 * q],     acc);
        acc = fmaf(wf1, sh_top[2 * q + 1], acc);
        acc += __shfl_xor_sync(0xffffffffu, acc, 1);
        acc += __shfl_xor_sync(0xffffffffu, acc, 2);
        if (q == 0) {
            const float hn = fast_tanh(acc + xp_cur);
            sh_h[nbuf][jgp] = hn;
            asm volatile("st.shared::cluster.f32 [%0], %1;"
                         :: "r"(peer_h + (uint32_t)((nbuf * HBUF + jgp) * 4)), "f"(hn)
                         : "memory");
        }
        xp_cur = xp_next;
        __syncthreads();                       // G

        if (tid == 0)
            asm volatile("mbarrier.arrive.release.cluster.shared::cluster.b64 _, [%0];"
                         :: "r"(peer_bar) : "memory");

        // ---- I: stack blend (overlaps peer DSMEM latency) -----------------
        {
            const float A0 = sh_a[0], A1 = sh_a[1], A2 = sh_a[2];
            #pragma unroll
            for (int rr = 0; rr < 2; rr++) {
                const int e = tid + rr * 512;
                const int p = e >> 3, d = e & 7;
                const float push = (p == 0)      ? sh_n[d] : sh_stack[buf][e - 8];
                const float pop  = (p == PD - 1) ? 0.f     : sh_stack[buf][e + 8];
                sh_stack[nbuf][e] = A0 * push + A1 * pop + A2 * sh_stack[buf][e];
            }
        }

        // ---- J: wait for peer half of h_{t+1} -----------------------------
        {
            const uint32_t par = (uint32_t)(t & 1);
            uint32_t done;
            do {
                asm volatile("{\n\t.reg .pred P;\n\t"
                    "mbarrier.try_wait.parity.acquire.cluster.shared::cta.b64 P, [%1], %2, 0x989680;\n\t"
                    "selp.b32 %0, 1, 0, P;\n\t}"
                    : "=r"(done) : "r"(bar_u32), "r"(par) : "memory");
            } while (!done);
        }
    }

    // ---- Epilogue: hidden_T in sh_h[0]; stack_{T-1} in sh_stack[0] --------
    // g_H[T-1] + final dots -> a,n -> stack_T -> outputs.
    if (wid < 11) {
        const float* wr = &sh_Wan[wid * PH];
        float p = 0.f;
        #pragma unroll
        for (int i = 0; i < 8; i++)
            p = fmaf(sh_h[0][(i >> 1) * HPAD + (i & 1) * 32 + lane],
                     wr[lane + 32 * i], p);
        #pragma unroll
        for (int o = 16; o > 0; o >>= 1)
            p += __shfl_xor_sync(0xffffffffu, p, o);
        if (lane == 0) sh_dots[wid] = p;
    } else if (wid >= 12) {
        const int i = tid - 384;
        g_H[((size_t)batch * PT + PT - 1) * PH + half * 128 + i] =
            sh_h[0][(half * 2 + (i >> 6)) * HPAD + (i & 63)];
    }
    __syncthreads();
    if (wid == 0) {
        const float d0 = sh_dots[0], d1 = sh_dots[1], d2 = sh_dots[2];
        const float mx = fmaxf(d0, fmaxf(d1, d2));
        const float e0 = __expf(d0 - mx), e1 = __expf(d1 - mx), e2 = __expf(d2 - mx);
        const float inv = __fdividef(1.f, e0 + e1 + e2);
        if (lane == 0) { sh_a[0] = e0 * inv; sh_a[1] = e1 * inv; sh_a[2] = e2 * inv; }
        if (lane < PVD)
            sh_n[lane] = __fdividef(1.f, 1.f + __expf(-sh_dots[3 + lane]));
    }
    __syncthreads();
    {
        const float A0 = sh_a[0], A1 = sh_a[1], A2 = sh_a[2];
        #pragma unroll
        for (int rr = 0; rr < 2; rr++) {
            const int e = tid + rr * 512;
            const int p = e >> 3, d = e & 7;
            const float push = (p == 0)      ? sh_n[d] : sh_stack[0][e - 8];
            const float pop  = (p == PD - 1) ? 0.f     : sh_stack[0][e + 8];
            sh_stack[1][e] = A0 * push + A1 * pop + A2 * sh_stack[0][e];
        }
    }
    __syncthreads();

    const size_t OUT_Y = (size_t)PB * PT * PV;
    if (half == 0) {
        for (int e = tid; e < PD * PVD; e += 512)
            out[OUT_Y + (size_t)batch * PD * PVD + e] = sh_stack[1][e];
    }
    if (tid < 128) {
        const int row = half * 128 + tid;
        out[OUT_Y + (size_t)PB * PD * PVD + (size_t)batch * PH + row] =
            sh_h[0][hpad_idx(row)];
    }

    asm volatile("barrier.cluster.arrive.aligned;" ::: "memory");
    asm volatile("barrier.cluster.wait.aligned;"   ::: "memory");
}

// ---------------------------------------------------------------------------
extern "C" void kernel_launch(void* const* d_in, const int* in_sizes, int n_in,
                              void* d_out, int out_size)
{
    const float* inputs  = (const float*)d_in[0];
    const float* stack0  = (const float*)d_in[1];
    const float* hidden0 = (const float*)d_in[2];
    const float* W_ih    = (const float*)d_in[3];
    const float* b_ih    = (const float*)d_in[4];
    const float* W_hh    = (const float*)d_in[5];
    const float* b_hh    = (const float*)d_in[6];
    const float* W_sh    = (const float*)d_in[7];
    const float* W_y     = (const float*)d_in[8];
    const float* W_a     = (const float*)d_in[9];
    const float* W_n     = (const float*)d_in[10];
    float* out = (float*)d_out;

    const int M = PB * PT;  // 131072

    fold_kernel<<<8, 256>>>(W_hh, W_sh);
    gemm_nt<<<dim3(M / 128, PH / 128), 256>>>(inputs, W_ih, b_ih, b_hh,
                                              nullptr, M, PH, PV, 1, 0);
    scan_kernel<<<2 * PB, 512>>>(stack0, hidden0, W_hh, W_a, W_n, out);
    gemm_nt<<<dim3(M / 128, PV / 128), 256>>>(nullptr, W_y, nullptr, nullptr,
                                              out, M, PV, PH, 0, 1);
}